// round 3
// baseline (speedup 1.0000x reference)
#include <cuda_runtime.h>

#define Bq 32
#define Tq 512
#define Hq 512
#define FFq 2048

typedef unsigned long long u64;

// ---------------- static device scratch (no runtime allocation) ---------------
__device__ float g_Uf[Bq*Tq*Hq];        // x @ Wf[0:D] + bf
__device__ float g_Ub[Bq*Tq*Hq];        // x @ Wb[0:D] + bb
__device__ float g_Z [Bq*Tq*2*Hq];      // concat(out_f, out_b), zeroed where masked
__device__ float g_A [Bq*Tq*FFq];       // tanh(Z@W1+b1)
__device__ float g_h [2*2*Bq*Hq];       // [dir][pingpong][b*H+j]
__device__ float g_S [Bq*2*Hq];         // concat(hT_f, hT_b)
__device__ float g_As[Bq*FFq];          // states hidden
__device__ unsigned g_bar;              // grid barrier (monotonic)

__device__ __forceinline__ u64 pk2(float lo, float hi) {
    u64 r; asm("mov.b64 %0, {%1, %2};" : "=l"(r) : "f"(lo), "f"(hi)); return r;
}
__device__ __forceinline__ void fma2(u64& d, u64 a, u64 b) {
    asm("fma.rn.f32x2 %0, %1, %2, %0;" : "+l"(d) : "l"(a), "l"(b));
}
__device__ __forceinline__ float2 upk(u64 v) {
    float2 f; asm("mov.b64 {%0, %1}, %2;" : "=f"(f.x), "=f"(f.y) : "l"(v)); return f;
}

// ---------------- init ---------------------------------------------------------
__global__ void init_kernel() {
    size_t idx = (size_t)blockIdx.x * blockDim.x + threadIdx.x;
    size_t stride = (size_t)gridDim.x * blockDim.x;
    float4 z = make_float4(0.f, 0.f, 0.f, 0.f);
    for (size_t i = idx; i < (size_t)(Bq*Tq*2*Hq)/4; i += stride) ((float4*)g_Z)[i] = z;
    for (size_t i = idx; i < (size_t)(2*2*Bq*Hq)/4; i += stride) ((float4*)g_h)[i] = z;
    if (idx == 0) g_bar = 0u;
}

// ---------------- generic 128x128x16 GEMM, fp32 via packed f32x2 ----------------
// C[M,N] = op(A[M,K] @ B[K,N] + bias[N]); act!=0 -> tanh. N%128==0, K%16==0.
__global__ void __launch_bounds__(256, 2) gemm_kernel(
    const float* __restrict__ A, const float* __restrict__ B,
    const float* __restrict__ bias, float* __restrict__ C,
    int M, int N, int K, int act)
{
    __shared__ u64   As_u[16][128];   // A value duplicated into both halves
    __shared__ float Bs[16][128];

    const int tid = threadIdx.x;
    const int bn = blockIdx.x, bm = blockIdx.y;
    const int tx = tid & 15, ty = tid >> 4;

    u64 acc[8][4];
    #pragma unroll
    for (int i = 0; i < 8; ++i)
        #pragma unroll
        for (int p = 0; p < 4; ++p) acc[i][p] = 0ull;

    const int arow = tid >> 1;
    const int acol = (tid & 1) * 8;
    const int brow = tid >> 4;
    const int bcol = (tid & 15) * 8;
    const int grow = bm * 128 + arow;
    const bool aok = grow < M;
    const float* Ap = A + (size_t)grow * K + acol;
    const float* Bp = B + (size_t)brow * N + bn * 128 + bcol;

    for (int k0 = 0; k0 < K; k0 += 16) {
        float4 a0 = make_float4(0.f,0.f,0.f,0.f), a1 = a0;
        if (aok) {
            a0 = *(const float4*)(Ap + k0);
            a1 = *(const float4*)(Ap + k0 + 4);
        }
        float4 b0 = *(const float4*)(Bp + (size_t)k0 * N);
        float4 b1 = *(const float4*)(Bp + (size_t)k0 * N + 4);
        __syncthreads();
        As_u[acol + 0][arow] = pk2(a0.x, a0.x);
        As_u[acol + 1][arow] = pk2(a0.y, a0.y);
        As_u[acol + 2][arow] = pk2(a0.z, a0.z);
        As_u[acol + 3][arow] = pk2(a0.w, a0.w);
        As_u[acol + 4][arow] = pk2(a1.x, a1.x);
        As_u[acol + 5][arow] = pk2(a1.y, a1.y);
        As_u[acol + 6][arow] = pk2(a1.z, a1.z);
        As_u[acol + 7][arow] = pk2(a1.w, a1.w);
        *(float4*)&Bs[brow][bcol]     = b0;
        *(float4*)&Bs[brow][bcol + 4] = b1;
        __syncthreads();

        #pragma unroll
        for (int kk = 0; kk < 16; ++kk) {
            u64 bb[4], aa[8];
            #pragma unroll
            for (int p = 0; p < 4; ++p)
                bb[p] = *(const u64*)&Bs[kk][tx * 8 + 2 * p];
            #pragma unroll
            for (int i = 0; i < 8; ++i)
                aa[i] = As_u[kk][ty * 8 + i];
            #pragma unroll
            for (int i = 0; i < 8; ++i)
                #pragma unroll
                for (int p = 0; p < 4; ++p)
                    fma2(acc[i][p], aa[i], bb[p]);
        }
    }

    const int gcol = bn * 128 + tx * 8;
    float bv[8];
    #pragma unroll
    for (int p = 0; p < 4; ++p) {
        float2 t = *(const float2*)&bias[gcol + 2 * p];
        bv[2*p] = t.x; bv[2*p+1] = t.y;
    }
    #pragma unroll
    for (int i = 0; i < 8; ++i) {
        int row = bm * 128 + ty * 8 + i;
        if (row < M) {
            float o[8];
            #pragma unroll
            for (int p = 0; p < 4; ++p) {
                float2 v = upk(acc[i][p]);
                o[2*p]   = v.x + bv[2*p];
                o[2*p+1] = v.y + bv[2*p+1];
            }
            if (act) {
                #pragma unroll
                for (int c = 0; c < 8; ++c) o[c] = tanhf(o[c]);
            }
            *(float4*)&C[(size_t)row * N + gcol]     = make_float4(o[0],o[1],o[2],o[3]);
            *(float4*)&C[(size_t)row * N + gcol + 4] = make_float4(o[4],o[5],o[6],o[7]);
        }
    }
}

// ---------------- persistent bidirectional RNN ---------------------------------
// grid = 128 CTAs (64 per direction), 256 threads. CTA owns 8 j-columns.
// Thread = (b, jl). Per step: stage h (L2, __ldcg) into smem, dot(h, Wh[:,j]),
// tanh(U + dot), masked update, grid barrier.
#define HS_STRIDE 520
#define WS_STRIDE 516
#define RNN_SMEM ((Bq*HS_STRIDE + 8*WS_STRIDE) * 4)

__global__ void __launch_bounds__(256, 1) rnn_kernel(
    const int* __restrict__ length,
    const float* __restrict__ Wf_h, const float* __restrict__ Wb_h)
{
    extern __shared__ float sm[];
    float* h_s = sm;                       // [32][HS_STRIDE]
    float* Whs = sm + Bq * HS_STRIDE;      // [8][WS_STRIDE]

    const int dir  = blockIdx.x >> 6;
    const int j0   = (blockIdx.x & 63) * 8;
    const int tid  = threadIdx.x;
    const int b    = tid >> 3;
    const int jl   = tid & 7;
    const int j    = j0 + jl;
    const float* W = dir ? Wb_h : Wf_h;
    const float* U = dir ? g_Ub : g_Uf;
    const int L    = length[b];
    float* hbase   = g_h + dir * 2 * (Bq*Hq);

    for (int i = tid; i < 8 * Hq; i += 256) {
        int kk = i >> 3, jj = i & 7;
        Whs[jj * WS_STRIDE + kk] = W[kk * Hq + j0 + jj];
    }

    for (int s = 0; s < Tq; ++s) {
        const float* hin = hbase + (s & 1) * (Bq*Hq);
        float* hout      = hbase + ((s + 1) & 1) * (Bq*Hq);

        for (int i = tid; i < (Bq*Hq)/4; i += 256) {
            int idx = i * 4;
            int bb_ = idx >> 9, kk = idx & 511;
            float4 v = __ldcg((const float4*)(hin + idx));
            *(float4*)&h_s[bb_ * HS_STRIDE + kk] = v;
        }
        __syncthreads();

        const float* hb = &h_s[b * HS_STRIDE];
        const float* wj = &Whs[jl * WS_STRIDE];
        u64 acc0 = 0ull, acc1 = 0ull;
        #pragma unroll 8
        for (int k = 0; k < Hq; k += 4) {
            u64 h0 = *(const u64*)(hb + k);
            u64 h1 = *(const u64*)(hb + k + 2);
            u64 w0 = *(const u64*)(wj + k);
            u64 w1 = *(const u64*)(wj + k + 2);
            fma2(acc0, h0, w0);
            fma2(acc1, h1, w1);
        }
        float2 p0 = upk(acc0), p1 = upk(acc1);
        float dot = (p0.x + p1.x) + (p0.y + p1.y);

        float hnew;
        if (s < L) {
            int t = dir ? (L - 1 - s) : s;
            float u = U[((size_t)(b * Tq + t)) * Hq + j];
            hnew = tanhf(u + dot);
            g_Z[((size_t)(b * Tq + t)) * (2*Hq) + dir * Hq + j] = hnew;
        } else {
            hnew = hb[j];
        }
        hout[b * Hq + j] = hnew;

        __threadfence();
        __syncthreads();
        if (tid == 0) {
            atomicAdd(&g_bar, 1u);
            unsigned tgt = (unsigned)(s + 1) * 128u;
            unsigned v;
            do {
                asm volatile("ld.acquire.gpu.u32 %0, [%1];" : "=r"(v) : "l"(&g_bar));
            } while (v < tgt);
        }
        __syncthreads();
    }
}

// ---------------- states assembly ----------------------------------------------
__global__ void states_kernel() {
    int i = blockIdx.x * blockDim.x + threadIdx.x;
    if (i < Bq * 2 * Hq) {
        int b = i >> 10, c = i & 1023;
        int dir = c >> 9, j = c & 511;
        // after 512 steps, final h lives in pingpong buffer 0
        g_S[i] = g_h[dir * 2 * (Bq*Hq) + b * Hq + j];
    }
}

// ---------------- launcher ------------------------------------------------------
extern "C" void kernel_launch(void* const* d_in, const int* in_sizes, int n_in,
                              void* d_out, int out_size) {
    const float* x      = (const float*)d_in[0];
    const int*   length = (const int*)  d_in[1];
    const float* Wf     = (const float*)d_in[2];
    const float* bf     = (const float*)d_in[3];
    const float* Wb     = (const float*)d_in[4];
    const float* bb     = (const float*)d_in[5];
    const float* W1     = (const float*)d_in[6];
    const float* b1     = (const float*)d_in[7];
    const float* W2     = (const float*)d_in[8];
    const float* b2     = (const float*)d_in[9];
    float* out = (float*)d_out;

    void *pUf, *pUb, *pZ, *pA, *pS, *pAs;
    cudaGetSymbolAddress(&pUf, g_Uf);
    cudaGetSymbolAddress(&pUb, g_Ub);
    cudaGetSymbolAddress(&pZ,  g_Z);
    cudaGetSymbolAddress(&pA,  g_A);
    cudaGetSymbolAddress(&pS,  g_S);
    cudaGetSymbolAddress(&pAs, g_As);

    cudaFuncSetAttribute(rnn_kernel, cudaFuncAttributeMaxDynamicSharedMemorySize, RNN_SMEM);

    const int M = Bq * Tq;   // 16384

    init_kernel<<<2048, 256>>>();

    // U_f = X @ Wf[0:D] + bf ; U_b = X @ Wb[0:D] + bb
    gemm_kernel<<<dim3(Hq/128, M/128), 256>>>(x, Wf, bf, (float*)pUf, M, Hq, Hq, 0);
    gemm_kernel<<<dim3(Hq/128, M/128), 256>>>(x, Wb, bb, (float*)pUb, M, Hq, Hq, 0);

    // recurrence (both directions)
    rnn_kernel<<<128, 256, RNN_SMEM>>>(length, Wf + Hq*Hq, Wb + Hq*Hq);

    // sequence FFN
    gemm_kernel<<<dim3(FFq/128, M/128), 256>>>((const float*)pZ, W1, b1, (float*)pA, M, FFq, 2*Hq, 1);
    gemm_kernel<<<dim3((2*Hq)/128, M/128), 256>>>((const float*)pA, W2, b2, out, M, 2*Hq, FFq, 0);

    // states FFN
    states_kernel<<<(Bq*2*Hq + 255)/256, 256>>>();
    gemm_kernel<<<dim3(FFq/128, 1), 256>>>((const float*)pS, W1, b1, (float*)pAs, Bq, FFq, 2*Hq, 1);
    gemm_kernel<<<dim3((2*Hq)/128, 1), 256>>>((const float*)pAs, W2, b2, out + (size_t)M * 2 * Hq, Bq, 2*Hq, FFq, 0);
}

// round 4
// speedup vs baseline: 1.1819x; 1.1819x over previous
#include <cuda_runtime.h>

#define Bq 32
#define Tq 512
#define Hq 512
#define FFq 2048

typedef unsigned long long u64;

// ---------------- static device scratch ---------------------------------------
__device__ float g_Uf[Bq*Tq*Hq];
__device__ float g_Ub[Bq*Tq*Hq];
__device__ float g_Z [Bq*Tq*2*Hq];
__device__ float g_A [Bq*Tq*FFq];
__device__ float g_h [2*2*Bq*Hq];       // [dir][pingpong][b*H+j]
__device__ float g_S [Bq*2*Hq];
__device__ float g_As[Bq*FFq];
__device__ unsigned g_bar;

__device__ __forceinline__ u64 pk2(float lo, float hi) {
    u64 r; asm("mov.b64 %0, {%1, %2};" : "=l"(r) : "f"(lo), "f"(hi)); return r;
}
__device__ __forceinline__ void fma2(u64& d, u64 a, u64 b) {
    asm("fma.rn.f32x2 %0, %1, %2, %0;" : "+l"(d) : "l"(a), "l"(b));
}
__device__ __forceinline__ float2 upk(u64 v) {
    float2 f; asm("mov.b64 {%0, %1}, %2;" : "=f"(f.x), "=f"(f.y) : "l"(v)); return f;
}

// ---------------- init ---------------------------------------------------------
__global__ void init_kernel() {
    size_t idx = (size_t)blockIdx.x * blockDim.x + threadIdx.x;
    size_t stride = (size_t)gridDim.x * blockDim.x;
    float4 z = make_float4(0.f, 0.f, 0.f, 0.f);
    for (size_t i = idx; i < (size_t)(Bq*Tq*2*Hq)/4; i += stride) ((float4*)g_Z)[i] = z;
    for (size_t i = idx; i < (size_t)(2*2*Bq*Hq)/4; i += stride) ((float4*)g_h)[i] = z;
    if (idx == 0) g_bar = 0u;
}

// ---------------- 128x128x16 fp32 GEMM via packed f32x2 -------------------------
// C = op(A[M,K] @ B[K,N] + bias); act -> tanh. N%128==0, K%16==0.
__global__ void __launch_bounds__(256, 2) gemm_kernel(
    const float* __restrict__ A, const float* __restrict__ B,
    const float* __restrict__ bias, float* __restrict__ C,
    int M, int N, int K, int act)
{
    __shared__ u64   As_u[16*128];   // [kk][row], value duplicated in both halves
    __shared__ float Bs[16*128];     // [kk][ first-halves(64) | second-halves(64) ]

    const int tid = threadIdx.x;
    const int bn = blockIdx.x, bm = blockIdx.y;
    const int tx = tid & 15, ty = tid >> 4;

    u64 acc[8][4];
    #pragma unroll
    for (int i = 0; i < 8; ++i)
        #pragma unroll
        for (int p = 0; p < 4; ++p) acc[i][p] = 0ull;

    const int arow = tid >> 1;
    const int acol = (tid & 1) * 8;
    const int brow = tid >> 4;
    const int grow = bm * 128 + arow;
    const bool aok = grow < M;
    const float* Ap = A + (size_t)grow * K + acol;
    const float* Bp = B + (size_t)brow * N + bn * 128 + tx * 8;

    float4 a0 = make_float4(0.f,0.f,0.f,0.f), a1 = a0;
    if (aok) { a0 = *(const float4*)(Ap); a1 = *(const float4*)(Ap + 4); }
    float4 b0 = *(const float4*)(Bp);
    float4 b1 = *(const float4*)(Bp + 4);

    for (int k0 = 0; k0 < K; k0 += 16) {
        __syncthreads();
        As_u[(acol + 0)*128 + arow] = pk2(a0.x, a0.x);
        As_u[(acol + 1)*128 + arow] = pk2(a0.y, a0.y);
        As_u[(acol + 2)*128 + arow] = pk2(a0.z, a0.z);
        As_u[(acol + 3)*128 + arow] = pk2(a0.w, a0.w);
        As_u[(acol + 4)*128 + arow] = pk2(a1.x, a1.x);
        As_u[(acol + 5)*128 + arow] = pk2(a1.y, a1.y);
        As_u[(acol + 6)*128 + arow] = pk2(a1.z, a1.z);
        As_u[(acol + 7)*128 + arow] = pk2(a1.w, a1.w);
        *(float4*)&Bs[brow*128 + tx*4]      = b0;
        *(float4*)&Bs[brow*128 + 64 + tx*4] = b1;
        __syncthreads();

        if (k0 + 16 < K) {
            if (aok) {
                a0 = *(const float4*)(Ap + k0 + 16);
                a1 = *(const float4*)(Ap + k0 + 20);
            }
            b0 = *(const float4*)(Bp + (size_t)(k0 + 16) * N);
            b1 = *(const float4*)(Bp + (size_t)(k0 + 16) * N + 4);
        }

        #pragma unroll
        for (int kk = 0; kk < 16; ++kk) {
            const u64* ap = &As_u[kk*128 + ty*8];
            ulonglong2 av0 = *(const ulonglong2*)(ap + 0);
            ulonglong2 av1 = *(const ulonglong2*)(ap + 2);
            ulonglong2 av2 = *(const ulonglong2*)(ap + 4);
            ulonglong2 av3 = *(const ulonglong2*)(ap + 6);
            ulonglong2 bv0 = *(const ulonglong2*)&Bs[kk*128 + tx*4];
            ulonglong2 bv1 = *(const ulonglong2*)&Bs[kk*128 + 64 + tx*4];
            u64 aa[8] = {av0.x, av0.y, av1.x, av1.y, av2.x, av2.y, av3.x, av3.y};
            u64 bb[4] = {bv0.x, bv0.y, bv1.x, bv1.y};
            #pragma unroll
            for (int i = 0; i < 8; ++i)
                #pragma unroll
                for (int p = 0; p < 4; ++p)
                    fma2(acc[i][p], aa[i], bb[p]);
        }
    }

    const int gcol = bn * 128 + tx * 8;
    float bv[8];
    #pragma unroll
    for (int p = 0; p < 4; ++p) {
        float2 t = *(const float2*)&bias[gcol + 2 * p];
        bv[2*p] = t.x; bv[2*p+1] = t.y;
    }
    #pragma unroll
    for (int i = 0; i < 8; ++i) {
        int row = bm * 128 + ty * 8 + i;
        if (row < M) {
            float o[8];
            #pragma unroll
            for (int p = 0; p < 4; ++p) {
                float2 v = upk(acc[i][p]);
                o[2*p]   = v.x + bv[2*p];
                o[2*p+1] = v.y + bv[2*p+1];
            }
            if (act) {
                #pragma unroll
                for (int c = 0; c < 8; ++c) o[c] = tanhf(o[c]);
            }
            *(float4*)&C[(size_t)row * N + gcol]     = make_float4(o[0],o[1],o[2],o[3]);
            *(float4*)&C[(size_t)row * N + gcol + 4] = make_float4(o[4],o[5],o[6],o[7]);
        }
    }
}

// ---------------- persistent bidirectional RNN ---------------------------------
// 128 CTAs x 256 threads. CTA = (dir, 8 j-columns). Warp w handles k-slice
// [w*64, w*64+64). Lane = (bi 0..7, ji 0..3); thread tile = 4 b x 2 j.
// h read directly from L2 (__ldcg), Wh slice in smem, cross-warp smem reduce.
__global__ void __launch_bounds__(256, 1) rnn_kernel(
    const int* __restrict__ length,
    const float* __restrict__ Wf_h, const float* __restrict__ Wb_h)
{
    __shared__ float Whs[8 * 516];     // [jl][k], stride 516
    __shared__ float red[8 * 288];     // [warp][b*9 + jl]

    const int tid  = threadIdx.x;
    const int wid  = tid >> 5;
    const int lane = tid & 31;
    const int bi   = lane >> 2;
    const int ji   = lane & 3;
    const int dir  = blockIdx.x >> 6;
    const int j0   = (blockIdx.x & 63) * 8;
    const float* W = dir ? Wb_h : Wf_h;
    const float* U = dir ? g_Ub : g_Uf;
    float* hbase   = g_h + dir * 2 * (Bq*Hq);

    // reduce-thread identity (fixed across steps)
    const int rb = tid >> 3;
    const int rj = tid & 7;
    const int L  = length[rb];
    float hprev = 0.f;

    for (int i = tid; i < 8 * Hq; i += 256) {
        int kk = i >> 3, jj = i & 7;
        Whs[jj * 516 + kk] = W[kk * Hq + j0 + jj];
    }
    __syncthreads();

    const int k0 = wid * 64;
    const int bA = bi * 4;

    for (int s = 0; s < Tq; ++s) {
        const float* hin = hbase + (s & 1) * (Bq*Hq);
        float* hout      = hbase + ((s + 1) & 1) * (Bq*Hq);

        u64 acc[4][2];
        #pragma unroll
        for (int ib = 0; ib < 4; ++ib) { acc[ib][0] = 0ull; acc[ib][1] = 0ull; }

        #pragma unroll 8
        for (int it = 0; it < 16; ++it) {
            int k = k0 + it * 4;
            float4 h0 = __ldcg((const float4*)(hin + (bA + 0) * Hq + k));
            float4 h1 = __ldcg((const float4*)(hin + (bA + 1) * Hq + k));
            float4 h2 = __ldcg((const float4*)(hin + (bA + 2) * Hq + k));
            float4 h3 = __ldcg((const float4*)(hin + (bA + 3) * Hq + k));
            ulonglong2 wA = *(const ulonglong2*)&Whs[(ji * 2 + 0) * 516 + k];
            ulonglong2 wB = *(const ulonglong2*)&Whs[(ji * 2 + 1) * 516 + k];
            const ulonglong2* hv;
            hv = (const ulonglong2*)&h0;
            fma2(acc[0][0], hv->x, wA.x); fma2(acc[0][0], hv->y, wA.y);
            fma2(acc[0][1], hv->x, wB.x); fma2(acc[0][1], hv->y, wB.y);
            hv = (const ulonglong2*)&h1;
            fma2(acc[1][0], hv->x, wA.x); fma2(acc[1][0], hv->y, wA.y);
            fma2(acc[1][1], hv->x, wB.x); fma2(acc[1][1], hv->y, wB.y);
            hv = (const ulonglong2*)&h2;
            fma2(acc[2][0], hv->x, wA.x); fma2(acc[2][0], hv->y, wA.y);
            fma2(acc[2][1], hv->x, wB.x); fma2(acc[2][1], hv->y, wB.y);
            hv = (const ulonglong2*)&h3;
            fma2(acc[3][0], hv->x, wA.x); fma2(acc[3][0], hv->y, wA.y);
            fma2(acc[3][1], hv->x, wB.x); fma2(acc[3][1], hv->y, wB.y);
        }

        #pragma unroll
        for (int ib = 0; ib < 4; ++ib)
            #pragma unroll
            for (int ij = 0; ij < 2; ++ij) {
                float2 p = upk(acc[ib][ij]);
                red[wid * 288 + (bA + ib) * 9 + (ji * 2 + ij)] = p.x + p.y;
            }
        __syncthreads();

        float dot = 0.f;
        #pragma unroll
        for (int w = 0; w < 8; ++w) dot += red[w * 288 + rb * 9 + rj];

        float hnew;
        if (s < L) {
            int t = dir ? (L - 1 - s) : s;
            float u = U[((size_t)(rb * Tq + t)) * Hq + j0 + rj];
            hnew = tanhf(u + dot);
            g_Z[((size_t)(rb * Tq + t)) * (2*Hq) + dir * Hq + j0 + rj] = hnew;
        } else {
            hnew = hprev;
        }
        hprev = hnew;
        hout[rb * Hq + j0 + rj] = hnew;

        __threadfence();
        __syncthreads();
        if (tid == 0) {
            atomicAdd(&g_bar, 1u);
            unsigned tgt = (unsigned)(s + 1) * 128u;
            unsigned v;
            do {
                asm volatile("ld.acquire.gpu.u32 %0, [%1];" : "=r"(v) : "l"(&g_bar));
            } while (v < tgt);
        }
        __syncthreads();
    }
}

// ---------------- states assembly ----------------------------------------------
__global__ void states_kernel() {
    int i = blockIdx.x * blockDim.x + threadIdx.x;
    if (i < Bq * 2 * Hq) {
        int b = i >> 10, c = i & 1023;
        int dir = c >> 9, j = c & 511;
        g_S[i] = g_h[dir * 2 * (Bq*Hq) + b * Hq + j];   // final h in pingpong buf 0
    }
}

// ---------------- launcher ------------------------------------------------------
extern "C" void kernel_launch(void* const* d_in, const int* in_sizes, int n_in,
                              void* d_out, int out_size) {
    const float* x      = (const float*)d_in[0];
    const int*   length = (const int*)  d_in[1];
    const float* Wf     = (const float*)d_in[2];
    const float* bf     = (const float*)d_in[3];
    const float* Wb     = (const float*)d_in[4];
    const float* bb     = (const float*)d_in[5];
    const float* W1     = (const float*)d_in[6];
    const float* b1     = (const float*)d_in[7];
    const float* W2     = (const float*)d_in[8];
    const float* b2     = (const float*)d_in[9];
    float* out = (float*)d_out;

    void *pUf, *pUb, *pZ, *pA, *pS, *pAs;
    cudaGetSymbolAddress(&pUf, g_Uf);
    cudaGetSymbolAddress(&pUb, g_Ub);
    cudaGetSymbolAddress(&pZ,  g_Z);
    cudaGetSymbolAddress(&pA,  g_A);
    cudaGetSymbolAddress(&pS,  g_S);
    cudaGetSymbolAddress(&pAs, g_As);

    const int M = Bq * Tq;   // 16384

    init_kernel<<<2048, 256>>>();

    gemm_kernel<<<dim3(Hq/128, M/128), 256>>>(x, Wf, bf, (float*)pUf, M, Hq, Hq, 0);
    gemm_kernel<<<dim3(Hq/128, M/128), 256>>>(x, Wb, bb, (float*)pUb, M, Hq, Hq, 0);

    rnn_kernel<<<128, 256>>>(length, Wf + Hq*Hq, Wb + Hq*Hq);

    gemm_kernel<<<dim3(FFq/128, M/128), 256>>>((const float*)pZ, W1, b1, (float*)pA, M, FFq, 2*Hq, 1);
    gemm_kernel<<<dim3((2*Hq)/128, M/128), 256>>>((const float*)pA, W2, b2, out, M, 2*Hq, FFq, 0);

    states_kernel<<<(Bq*2*Hq + 255)/256, 256>>>();
    gemm_kernel<<<dim3(FFq/128, 1), 256>>>((const float*)pS, W1, b1, (float*)pAs, Bq, FFq, 2*Hq, 1);
    gemm_kernel<<<dim3((2*Hq)/128, 1), 256>>>((const float*)pAs, W2, b2, out + (size_t)M * 2 * Hq, Bq, 2*Hq, FFq, 0);
}